// round 13
// baseline (speedup 1.0000x reference)
#include <cuda_runtime.h>
#include <cuda_fp16.h>
#include <cstdint>

// ---------------------------------------------------------------------------
// Problem constants
// ---------------------------------------------------------------------------
#define BATCH  256
#define LIN    2048
#define HNODE  256
#define GLEN   24
#define LOUT   2025
#define TWOH   512
#define KDIM   96
#define NTLOC  8              // tiles of 128 l-positions per CTA (l-half)
#define PLANE  2080           // l-entries per channel-pair plane
#define SLOTS  (2 * PLANE)    // g_xq slots per batch: [p][l] planes

__device__ float    g_pp[BATCH * 2 * TWOH];   // per (b, l-half): [max | sum]
__device__ uint32_t g_wA[2 * 8 * 32 * 24];    // pre-packed fp16 A-fragments
__device__ uint4    g_xq[BATCH * SLOTS];      // b-fragment quads, [b][p][l]

// ---------------------------------------------------------------------------
// Helpers
// ---------------------------------------------------------------------------
static __device__ __forceinline__ void hsplit(float v, unsigned short& hi,
                                              unsigned short& lo) {
    __half h = __float2half(v);
    __half l = __float2half(v - __half2float(h));
    hi = __half_as_ushort(h);
    lo = __half_as_ushort(l);
}

static __device__ __forceinline__ void mma_f16(float* d, const uint32_t* a,
                                               uint32_t b0, uint32_t b1) {
    asm volatile(
        "mma.sync.aligned.m16n8k16.row.col.f32.f16.f16.f32 "
        "{%0,%1,%2,%3}, {%4,%5,%6,%7}, {%8,%9}, {%0,%1,%2,%3};"
        : "+f"(d[0]), "+f"(d[1]), "+f"(d[2]), "+f"(d[3])
        : "r"(a[0]), "r"(a[1]), "r"(a[2]), "r"(a[3]), "r"(b0), "r"(b1));
}

// ---------------------------------------------------------------------------
// Kernel 0: unified prep. Plane layout makes reads AND writes sequential:
//   thread j of batch b: p = j/2080, l = j%2080
//   g_xq[b*SLOTS + j] = {xh(c2p,l)|xh(c2p+1,l), same@l+2, xl..., xl...@l+2}
// ---------------------------------------------------------------------------
__global__ void __launch_bounds__(256)
prep_kernel(const float* __restrict__ x, const float* __restrict__ wConv) {
    const int bid = blockIdx.x;
    const int tid = threadIdx.x;

    if (bid < 4160) {
        const int id = bid * 256 + tid;          // 256 batches * 4160
        const int b  = id / SLOTS;
        const int j  = id % SLOTS;
        const int p  = j / PLANE;
        const int l  = j % PLANE;
        const float* xb = x + (size_t)b * 4 * LIN + (size_t)(2 * p) * LIN;

        float f00 = 0.f, f10 = 0.f, f01 = 0.f, f11 = 0.f;
        if (l < LIN)     { f00 = xb[l];       f10 = xb[LIN + l]; }
        if (l + 2 < LIN) { f01 = xb[l + 2];   f11 = xb[LIN + l + 2]; }

        unsigned short h00, l00, h10, l10, h01, l01, h11, l11;
        hsplit(f00, h00, l00);
        hsplit(f10, h10, l10);
        hsplit(f01, h01, l01);
        hsplit(f11, h11, l11);

        uint4 q;
        q.x = (uint32_t)h00 | ((uint32_t)h10 << 16);
        q.y = (uint32_t)h01 | ((uint32_t)h11 << 16);
        q.z = (uint32_t)l00 | ((uint32_t)l10 << 16);
        q.w = (uint32_t)l01 | ((uint32_t)l11 << 16);
        g_xq[id] = q;
    } else {
        const int id = (bid - 4160) * 256 + tid;   // < 12288
        const int mh   = id / 6144;
        const int rem  = id % 6144;
        const int wm   = rem / 768;
        const int rem2 = rem % 768;
        const int lane = rem2 / 24;
        const int j    = rem2 % 24;
        const int ks   = j >> 2;
        const int rr   = j & 3;
        const int grp  = lane >> 2;
        const int tg   = lane & 3;

        const int r  = wm * 16 + grp + (rr & 1) * 8;
        const int k0 = ks * 16 + tg * 2 + (rr >> 1) * 8;        // even
        const int base = (mh * 128 + r) * KDIM + (k0 >> 2);     // k = 4g + c
        const float f0 = wConv[base + (k0 & 3) * GLEN];
        const float f1 = wConv[base + ((k0 & 3) + 1) * GLEN];
        const unsigned short h0 = __half_as_ushort(__float2half(f0));
        const unsigned short h1 = __half_as_ushort(__float2half(f1));
        g_wA[id] = (uint32_t)h0 | ((uint32_t)h1 << 16);
    }
}

// ---------------------------------------------------------------------------
// Kernel 1: implicit-GEMM conv, 2-term fp16 split, gmem-direct b-fragments
// (round-11 structure: 1024 CTAs x 512 threads, 1 CTA/SM, no staging).
// Plane-layout slots: slot(nt,ks) = (tg&1)*2080 + L0 + ta*128 + wn*64 + grp
//                                   + (tg>>1) + 4*(2nt+ks)
// Diagonal reuse: even u -> +8j, odd u -> +4+8j. 20 LDG.128/warp/tile.
// ---------------------------------------------------------------------------
__global__ void __launch_bounds__(512, 1)
conv_mma_kernel(const float* __restrict__ wRect) {
    __shared__ float red[512];

    const int tid   = threadIdx.x;
    const int lane  = tid & 31;
    const int wid   = tid >> 5;
    const int b     = blockIdx.x >> 2;
    const int mh    = (blockIdx.x >> 1) & 1;
    const int lq    = blockIdx.x & 1;
    const int hbase = mh * 128;
    const int L0    = lq * 1024;
    const int wm    = wid & 7;
    const int wn    = wid >> 3;
    const int grp   = lane >> 2;
    const int tg    = lane & 3;
    const int kq    = tg * 2;

    // ---- A fragments: 6 x LDG.128 from the pre-packed layout ----
    uint32_t aH[6][4];
    {
        const uint32_t* wa = g_wA + ((size_t)((mh * 8 + wm) * 32 + lane)) * 24;
#pragma unroll
        for (int ks = 0; ks < 6; ++ks)
            *(uint4*)&aH[ks][0] = *(const uint4*)(wa + ks * 4);
    }

    float rb[2];
    rb[0] = wRect[hbase + wm * 16 + grp];
    rb[1] = wRect[hbase + wm * 16 + 8 + grp];

    // b-fragment table (gmem; L1-cached on reuse), plane layout
    const uint4* XiQ = g_xq + (size_t)b * SLOTS;
    const int sbase = (tg & 1) * PLANE + L0 + wn * 64 + grp + (tg >> 1);
    const int toff  = (wid >> 2) << 1;

    float mx[2] = {0.f, 0.f};
    float sm[2] = {0.f, 0.f};

    for (int t = 0; t < NTLOC; ++t) {
        const int ta = (t + toff) & 7;
        const int base_t = sbase + ta * 128;

        float d[8][4];
#pragma unroll
        for (int nt = 0; nt < 8; ++nt) {
            d[nt][0] = rb[0]; d[nt][1] = rb[0];
            d[nt][2] = rb[1]; d[nt][3] = rb[1];
        }

        uint4 q[10];

        // ---- even parity: u = 2j -> serves ks = 0,2,4 ----
#pragma unroll
        for (int j = 0; j < 10; ++j)
            q[j] = XiQ[base_t + 8 * j];
#pragma unroll
        for (int kk = 0; kk < 3; ++kk) {
#pragma unroll
            for (int nt = 0; nt < 8; ++nt)
                mma_f16(d[nt], aH[2 * kk], q[nt + kk].x, q[nt + kk].y);
#pragma unroll
            for (int nt = 0; nt < 8; ++nt)
                mma_f16(d[nt], aH[2 * kk], q[nt + kk].z, q[nt + kk].w);
        }

        // ---- odd parity: u = 2j+1 -> serves ks = 1,3,5 ----
#pragma unroll
        for (int j = 0; j < 10; ++j)
            q[j] = XiQ[base_t + 4 + 8 * j];
#pragma unroll
        for (int kk = 0; kk < 3; ++kk) {
#pragma unroll
            for (int nt = 0; nt < 8; ++nt)
                mma_f16(d[nt], aH[2 * kk + 1], q[nt + kk].x, q[nt + kk].y);
#pragma unroll
            for (int nt = 0; nt < 8; ++nt)
                mma_f16(d[nt], aH[2 * kk + 1], q[nt + kk].z, q[nt + kk].w);
        }

        if (!(lq == 1 && ta == 7)) {
#pragma unroll
            for (int nt = 0; nt < 8; ++nt)
#pragma unroll
                for (int e = 0; e < 4; ++e) {
                    const int rh = e >> 1;
                    const float r = fmaxf(d[nt][e], 0.f);
                    mx[rh] = fmaxf(mx[rh], r);
                    sm[rh] += r;
                }
        } else {
            const int lb = L0 + ta * 128 + wn * 64;
#pragma unroll
            for (int nt = 0; nt < 8; ++nt)
#pragma unroll
                for (int e = 0; e < 4; ++e) {
                    const int rh = e >> 1;
                    const int n  = lb + nt * 8 + kq + (e & 1);
                    const float r = fmaxf(d[nt][e], 0.f);
                    if (n < LOUT) {
                        mx[rh] = fmaxf(mx[rh], r);
                        sm[rh] += r;
                    }
                }
        }
    }

    // ---- lane-group reduce, cross-wn combine, write partials ----
#pragma unroll
    for (int rh = 0; rh < 2; ++rh) {
        float mv = mx[rh], sv = sm[rh];
        mv = fmaxf(mv, __shfl_xor_sync(0xffffffffu, mv, 1));
        sv +=        __shfl_xor_sync(0xffffffffu, sv, 1);
        mv = fmaxf(mv, __shfl_xor_sync(0xffffffffu, mv, 2));
        sv +=        __shfl_xor_sync(0xffffffffu, sv, 2);
        if (tg == 0) {
            const int m = wm * 16 + rh * 8 + grp;
            red[wn * 128 + m]       = mv;
            red[256 + wn * 128 + m] = sv;
        }
    }
    __syncthreads();

    if (tid < 128) {
        const float mv = fmaxf(red[tid], red[128 + tid]);
        const float sv = red[256 + tid] + red[384 + tid];
        float* pp = g_pp + (size_t)(b * 2 + lq) * TWOH;
        pp[hbase + tid]         = mv;
        pp[HNODE + hbase + tid] = sv;      // unscaled sum
    }
}

// ---------------------------------------------------------------------------
// Kernel 2: fused MLP head. 32 CTAs x 512 threads, 8 batches each.
// ---------------------------------------------------------------------------
__global__ void __launch_bounds__(512)
mlp_kernel(const float* __restrict__ wH, const float* __restrict__ wHB,
           const float* __restrict__ wNeu, const float* __restrict__ wNB,
           float* __restrict__ out) {
    __shared__ float4 prow[2][TWOH];
    __shared__ float  redsm[128];

    const int tid = threadIdx.x;
    const int b0  = blockIdx.x * 8;
    const int o   = tid;

    {
        const int i = tid;
        const float inv = 1.0f / LOUT;
#pragma unroll
        for (int h = 0; h < 2; ++h) {
            float4 v;
#pragma unroll
            for (int j = 0; j < 4; ++j) {
                const int bb = b0 + h * 4 + j;
                const float* p0 = g_pp + (size_t)(bb * 2 + 0) * TWOH;
                const float* p1 = g_pp + (size_t)(bb * 2 + 1) * TWOH;
                ((float*)&v)[j] = (i < HNODE) ? fmaxf(p0[i], p1[i])
                                              : (p0[i] + p1[i]) * inv;
            }
            prow[h][i] = v;
        }
    }
    __syncthreads();

    float a[8];
#pragma unroll
    for (int j = 0; j < 8; ++j) a[j] = 0.f;
#pragma unroll 4
    for (int i = 0; i < TWOH; ++i) {
        const float w = wH[i * TWOH + o];
        const float4 p0 = prow[0][i];
        const float4 p1 = prow[1][i];
        a[0] = fmaf(p0.x, w, a[0]);
        a[1] = fmaf(p0.y, w, a[1]);
        a[2] = fmaf(p0.z, w, a[2]);
        a[3] = fmaf(p0.w, w, a[3]);
        a[4] = fmaf(p1.x, w, a[4]);
        a[5] = fmaf(p1.y, w, a[5]);
        a[6] = fmaf(p1.z, w, a[6]);
        a[7] = fmaf(p1.w, w, a[7]);
    }

    const float hb = wHB[o];
    const float wv = wNeu[o];
    const int lane = tid & 31, wid = tid >> 5;
#pragma unroll
    for (int j = 0; j < 8; ++j) {
        float v = fmaxf(a[j] + hb, 0.f) * wv;
        v += __shfl_xor_sync(0xffffffffu, v, 16);
        v += __shfl_xor_sync(0xffffffffu, v, 8);
        v += __shfl_xor_sync(0xffffffffu, v, 4);
        v += __shfl_xor_sync(0xffffffffu, v, 2);
        v += __shfl_xor_sync(0xffffffffu, v, 1);
        if (lane == 0) redsm[j * 16 + wid] = v;
    }
    __syncthreads();

    if (tid < 8) {
        float s = 0.f;
#pragma unroll
        for (int i = 0; i < 16; ++i) s += redsm[tid * 16 + i];
        out[b0 + tid] = 0.5f * s + wNB[0];
    }
}

// ---------------------------------------------------------------------------
// Launch
// ---------------------------------------------------------------------------
extern "C" void kernel_launch(void* const* d_in, const int* in_sizes, int n_in,
                              void* d_out, int out_size) {
    const float* x     = (const float*)d_in[0];
    const float* wConv = (const float*)d_in[1];
    const float* wRect = (const float*)d_in[2];
    const float* wH    = (const float*)d_in[3];
    const float* wHB   = (const float*)d_in[4];
    const float* wNeu  = (const float*)d_in[5];
    const float* wNB   = (const float*)d_in[6];
    float* out = (float*)d_out;

    prep_kernel<<<4208, 256>>>(x, wConv);
    conv_mma_kernel<<<BATCH * 4, 512>>>(wRect);
    mlp_kernel<<<32, 512>>>(wH, wHB, wNeu, wNB, out);
}

// round 14
// speedup vs baseline: 1.4380x; 1.4380x over previous
#include <cuda_runtime.h>
#include <cuda_fp16.h>
#include <cstdint>

// ---------------------------------------------------------------------------
// Problem constants
// ---------------------------------------------------------------------------
#define BATCH  256
#define LIN    2048
#define HNODE  256
#define GLEN   24
#define LOUT   2025
#define TWOH   512
#define KDIM   96
#define NTLOC  8              // tiles of 128 l-positions per CTA (l-half)
#define SLOTS  4176           // g_xq entries per batch (word-indexed)

__device__ float    g_pp[BATCH * 2 * TWOH];   // per (b, l-half): [max | sum]
__device__ uint32_t g_wA[2 * 8 * 32 * 24];    // pre-packed fp16 A-fragments
__device__ uint4    g_xq[BATCH * SLOTS];      // entry[i] = {TH(i),TH(i+4),TH(i+8),TH(i+12)}

// ---------------------------------------------------------------------------
// Helpers
// ---------------------------------------------------------------------------
static __device__ __forceinline__ uint32_t hpack(float a, float b) {
    const unsigned short ha = __half_as_ushort(__float2half(a));
    const unsigned short hb = __half_as_ushort(__float2half(b));
    return (uint32_t)ha | ((uint32_t)hb << 16);
}

static __device__ __forceinline__ void mma_f16(float* d, const uint32_t* a,
                                               uint32_t b0, uint32_t b1) {
    asm volatile(
        "mma.sync.aligned.m16n8k16.row.col.f32.f16.f16.f32 "
        "{%0,%1,%2,%3}, {%4,%5,%6,%7}, {%8,%9}, {%0,%1,%2,%3};"
        : "+f"(d[0]), "+f"(d[1]), "+f"(d[2]), "+f"(d[3])
        : "r"(a[0]), "r"(a[1]), "r"(a[2]), "r"(a[3]), "r"(b0), "r"(b1));
}

// ---------------------------------------------------------------------------
// Kernel 0: unified prep.
//  blocks [0, 4176):    g_xq. TH word w = 2l+p is the fp16 pair
//                       {x(2p,l), x(2p+1,l)}. entry[i] packs words
//                       i, i+4, i+8, i+12 -> one LDG.128 serves fragment
//                       u=2j (.x,.y) and u=2j+1 (.z,.w).
//  blocks [4176, 4224): g_wA lane-major fp16 A-fragments.
// ---------------------------------------------------------------------------
__global__ void __launch_bounds__(256)
prep_kernel(const float* __restrict__ x, const float* __restrict__ wConv) {
    const int bid = blockIdx.x;
    const int tid = threadIdx.x;

    if (bid < 4176) {
        const int id = bid * 256 + tid;        // 256 batches * 4176 entries
        const int b  = id / SLOTS;
        const int i  = id % SLOTS;
        const int l  = i >> 1;
        const int p  = i & 1;
        const float* xb = x + (size_t)b * 4 * LIN + (size_t)(2 * p) * LIN;

        uint32_t w[4];
#pragma unroll
        for (int j = 0; j < 4; ++j) {
            const int ll = l + 2 * j;          // words i+4j -> l + 2j
            float c0 = 0.f, c1 = 0.f;
            if (ll < LIN) { c0 = xb[ll]; c1 = xb[LIN + ll]; }
            w[j] = hpack(c0, c1);
        }
        uint4 q; q.x = w[0]; q.y = w[1]; q.z = w[2]; q.w = w[3];
        g_xq[id] = q;
    } else {
        const int id = (bid - 4176) * 256 + tid;   // < 12288
        const int mh   = id / 6144;
        const int rem  = id % 6144;
        const int wm   = rem / 768;
        const int rem2 = rem % 768;
        const int lane = rem2 / 24;
        const int j    = rem2 % 24;
        const int ks   = j >> 2;
        const int rr   = j & 3;
        const int grp  = lane >> 2;
        const int tg   = lane & 3;

        const int r  = wm * 16 + grp + (rr & 1) * 8;
        const int k0 = ks * 16 + tg * 2 + (rr >> 1) * 8;        // even
        const int base = (mh * 128 + r) * KDIM + (k0 >> 2);     // k = 4g + c
        g_wA[id] = hpack(wConv[base + (k0 & 3) * GLEN],
                         wConv[base + ((k0 & 3) + 1) * GLEN]);
    }
}

// ---------------------------------------------------------------------------
// Kernel 1: implicit-GEMM conv, SINGLE-term fp16 (W and x both fp16),
// gmem-direct fragments, paired-parity 16B entries.
// Per warp per tile: 10 LDG.128 + 24 HMMA. Same-acc spacing 8.
// Grid: 1024 CTAs = (batch, h-half, l-half). 512 threads = 16 warps,
// warp grid 8(M) x 2(N), warp tile 16(h) x 64(l). Per-warp tile stagger.
// ---------------------------------------------------------------------------
__global__ void __launch_bounds__(512, 1)
conv_mma_kernel(const float* __restrict__ wRect) {
    __shared__ float red[512];

    const int tid   = threadIdx.x;
    const int lane  = tid & 31;
    const int wid   = tid >> 5;
    const int b     = blockIdx.x >> 2;
    const int mh    = (blockIdx.x >> 1) & 1;
    const int lq    = blockIdx.x & 1;
    const int hbase = mh * 128;
    const int L0    = lq * 1024;
    const int wm    = wid & 7;
    const int wn    = wid >> 3;
    const int grp   = lane >> 2;
    const int tg    = lane & 3;
    const int kq    = tg * 2;

    // ---- A fragments: 6 x LDG.128 from the pre-packed layout ----
    uint32_t aH[6][4];
    {
        const uint32_t* wa = g_wA + ((size_t)((mh * 8 + wm) * 32 + lane)) * 24;
#pragma unroll
        for (int ks = 0; ks < 6; ++ks)
            *(uint4*)&aH[ks][0] = *(const uint4*)(wa + ks * 4);
    }

    float rb[2];
    rb[0] = wRect[hbase + wm * 16 + grp];
    rb[1] = wRect[hbase + wm * 16 + 8 + grp];

    // fragment entry table window (gmem; L1-cached on reuse)
    const uint4* XiQ = g_xq + (size_t)b * SLOTS + 2 * L0;
    const int sbase = 2 * (wn * 64 + grp + (tg >> 1)) + (tg & 1);
    const int toff  = (wid >> 2) << 1;    // SMSP-mates get different tiles

    float mx[2] = {0.f, 0.f};
    float sm[2] = {0.f, 0.f};

    for (int t = 0; t < NTLOC; ++t) {
        const int ta = (t + toff) & 7;
        const int base_t = sbase + 2 * ta * 128;

        float d[8][4];
#pragma unroll
        for (int nt = 0; nt < 8; ++nt) {
            d[nt][0] = rb[0]; d[nt][1] = rb[0];
            d[nt][2] = rb[1]; d[nt][3] = rb[1];
        }

        // ---- 10 paired-parity entries: Q[j] covers u = 2j and 2j+1 ----
        uint4 Q[10];
#pragma unroll
        for (int j = 0; j < 10; ++j)
            Q[j] = XiQ[base_t + 16 * j];

        // even ks = 2kk: fragment u = 2(nt+kk) -> Q[nt+kk].xy
#pragma unroll
        for (int kk = 0; kk < 3; ++kk)
#pragma unroll
            for (int nt = 0; nt < 8; ++nt)
                mma_f16(d[nt], aH[2 * kk], Q[nt + kk].x, Q[nt + kk].y);

        // odd ks = 2kk+1: fragment u = 2(nt+kk)+1 -> Q[nt+kk].zw
#pragma unroll
        for (int kk = 0; kk < 3; ++kk)
#pragma unroll
            for (int nt = 0; nt < 8; ++nt)
                mma_f16(d[nt], aH[2 * kk + 1], Q[nt + kk].z, Q[nt + kk].w);

        if (!(lq == 1 && ta == 7)) {
#pragma unroll
            for (int nt = 0; nt < 8; ++nt)
#pragma unroll
                for (int e = 0; e < 4; ++e) {
                    const int rh = e >> 1;
                    const float r = fmaxf(d[nt][e], 0.f);
                    mx[rh] = fmaxf(mx[rh], r);
                    sm[rh] += r;
                }
        } else {
            const int lb = L0 + ta * 128 + wn * 64;
#pragma unroll
            for (int nt = 0; nt < 8; ++nt)
#pragma unroll
                for (int e = 0; e < 4; ++e) {
                    const int rh = e >> 1;
                    const int n  = lb + nt * 8 + kq + (e & 1);
                    const float r = fmaxf(d[nt][e], 0.f);
                    if (n < LOUT) {
                        mx[rh] = fmaxf(mx[rh], r);
                        sm[rh] += r;
                    }
                }
        }
    }

    // ---- lane-group reduce, cross-wn combine, write partials ----
#pragma unroll
    for (int rh = 0; rh < 2; ++rh) {
        float mv = mx[rh], sv = sm[rh];
        mv = fmaxf(mv, __shfl_xor_sync(0xffffffffu, mv, 1));
        sv +=        __shfl_xor_sync(0xffffffffu, sv, 1);
        mv = fmaxf(mv, __shfl_xor_sync(0xffffffffu, mv, 2));
        sv +=        __shfl_xor_sync(0xffffffffu, sv, 2);
        if (tg == 0) {
            const int m = wm * 16 + rh * 8 + grp;
            red[wn * 128 + m]       = mv;
            red[256 + wn * 128 + m] = sv;
        }
    }
    __syncthreads();

    if (tid < 128) {
        const float mv = fmaxf(red[tid], red[128 + tid]);
        const float sv = red[256 + tid] + red[384 + tid];
        float* pp = g_pp + (size_t)(b * 2 + lq) * TWOH;
        pp[hbase + tid]         = mv;
        pp[HNODE + hbase + tid] = sv;      // unscaled sum
    }
}

// ---------------------------------------------------------------------------
// Kernel 2: fused MLP head. 32 CTAs x 512 threads, 8 batches each.
// ---------------------------------------------------------------------------
__global__ void __launch_bounds__(512)
mlp_kernel(const float* __restrict__ wH, const float* __restrict__ wHB,
           const float* __restrict__ wNeu, const float* __restrict__ wNB,
           float* __restrict__ out) {
    __shared__ float4 prow[2][TWOH];
    __shared__ float  redsm[128];

    const int tid = threadIdx.x;
    const int b0  = blockIdx.x * 8;
    const int o   = tid;

    {
        const int i = tid;
        const float inv = 1.0f / LOUT;
#pragma unroll
        for (int h = 0; h < 2; ++h) {
            float4 v;
#pragma unroll
            for (int j = 0; j < 4; ++j) {
                const int bb = b0 + h * 4 + j;
                const float* p0 = g_pp + (size_t)(bb * 2 + 0) * TWOH;
                const float* p1 = g_pp + (size_t)(bb * 2 + 1) * TWOH;
                ((float*)&v)[j] = (i < HNODE) ? fmaxf(p0[i], p1[i])
                                              : (p0[i] + p1[i]) * inv;
            }
            prow[h][i] = v;
        }
    }
    __syncthreads();

    float a[8];
#pragma unroll
    for (int j = 0; j < 8; ++j) a[j] = 0.f;
#pragma unroll 4
    for (int i = 0; i < TWOH; ++i) {
        const float w = wH[i * TWOH + o];
        const float4 p0 = prow[0][i];
        const float4 p1 = prow[1][i];
        a[0] = fmaf(p0.x, w, a[0]);
        a[1] = fmaf(p0.y, w, a[1]);
        a[2] = fmaf(p0.z, w, a[2]);
        a[3] = fmaf(p0.w, w, a[3]);
        a[4] = fmaf(p1.x, w, a[4]);
        a[5] = fmaf(p1.y, w, a[5]);
        a[6] = fmaf(p1.z, w, a[6]);
        a[7] = fmaf(p1.w, w, a[7]);
    }

    const float hb = wHB[o];
    const float wv = wNeu[o];
    const int lane = tid & 31, wid = tid >> 5;
#pragma unroll
    for (int j = 0; j < 8; ++j) {
        float v = fmaxf(a[j] + hb, 0.f) * wv;
        v += __shfl_xor_sync(0xffffffffu, v, 16);
        v += __shfl_xor_sync(0xffffffffu, v, 8);
        v += __shfl_xor_sync(0xffffffffu, v, 4);
        v += __shfl_xor_sync(0xffffffffu, v, 2);
        v += __shfl_xor_sync(0xffffffffu, v, 1);
        if (lane == 0) redsm[j * 16 + wid] = v;
    }
    __syncthreads();

    if (tid < 8) {
        float s = 0.f;
#pragma unroll
        for (int i = 0; i < 16; ++i) s += redsm[tid * 16 + i];
        out[b0 + tid] = 0.5f * s + wNB[0];
    }
}

// ---------------------------------------------------------------------------
// Launch
// ---------------------------------------------------------------------------
extern "C" void kernel_launch(void* const* d_in, const int* in_sizes, int n_in,
                              void* d_out, int out_size) {
    const float* x     = (const float*)d_in[0];
    const float* wConv = (const float*)d_in[1];
    const float* wRect = (const float*)d_in[2];
    const float* wH    = (const float*)d_in[3];
    const float* wHB   = (const float*)d_in[4];
    const float* wNeu  = (const float*)d_in[5];
    const float* wNB   = (const float*)d_in[6];
    float* out = (float*)d_out;

    prep_kernel<<<4224, 256>>>(x, wConv);
    conv_mma_kernel<<<BATCH * 4, 512>>>(wRect);
    mlp_kernel<<<32, 512>>>(wH, wHB, wNeu, wNB, out);
}

// round 16
// speedup vs baseline: 1.4428x; 1.0033x over previous
#include <cuda_runtime.h>
#include <cuda_fp16.h>
#include <cstdint>

// ---------------------------------------------------------------------------
// Problem constants
// ---------------------------------------------------------------------------
#define BATCH  256
#define LIN    2048
#define HNODE  256
#define GLEN   24
#define LOUT   2025
#define TWOH   512
#define KDIM   96
#define NTLOC  8              // tiles of 128 l-positions per CTA (l-half)
#define SLOTS  4176           // g_xq entries per batch (word-indexed)

__device__ float    g_pp[BATCH * 2 * TWOH];   // per (b, l-half): [max | sum]
__device__ uint32_t g_wA[2 * 8 * 32 * 24];    // pre-packed fp16 A-fragments
__device__ uint4    g_xq[BATCH * SLOTS];      // entry[i] = {TH(i),TH(i+4),TH(i+8),TH(i+12)}

// ---------------------------------------------------------------------------
// Helpers
// ---------------------------------------------------------------------------
static __device__ __forceinline__ uint32_t hpack(float a, float b) {
    const unsigned short ha = __half_as_ushort(__float2half(a));
    const unsigned short hb = __half_as_ushort(__float2half(b));
    return (uint32_t)ha | ((uint32_t)hb << 16);
}

// D = A*B + C  (C != D allowed -> accumulators start as bias, no init MOVs)
static __device__ __forceinline__ void mma_f16_c(float* d, const uint32_t* a,
                                                 uint32_t b0, uint32_t b1,
                                                 const float* c) {
    asm volatile(
        "mma.sync.aligned.m16n8k16.row.col.f32.f16.f16.f32 "
        "{%0,%1,%2,%3}, {%4,%5,%6,%7}, {%8,%9}, {%10,%11,%12,%13};"
        : "=f"(d[0]), "=f"(d[1]), "=f"(d[2]), "=f"(d[3])
        : "r"(a[0]), "r"(a[1]), "r"(a[2]), "r"(a[3]), "r"(b0), "r"(b1),
          "f"(c[0]), "f"(c[1]), "f"(c[2]), "f"(c[3]));
}

static __device__ __forceinline__ void mma_f16(float* d, const uint32_t* a,
                                               uint32_t b0, uint32_t b1) {
    asm volatile(
        "mma.sync.aligned.m16n8k16.row.col.f32.f16.f16.f32 "
        "{%0,%1,%2,%3}, {%4,%5,%6,%7}, {%8,%9}, {%0,%1,%2,%3};"
        : "+f"(d[0]), "+f"(d[1]), "+f"(d[2]), "+f"(d[3])
        : "r"(a[0]), "r"(a[1]), "r"(a[2]), "r"(a[3]), "r"(b0), "r"(b1));
}

// ---------------------------------------------------------------------------
// Kernel 0: unified prep (unchanged from round 14)
// ---------------------------------------------------------------------------
__global__ void __launch_bounds__(256)
prep_kernel(const float* __restrict__ x, const float* __restrict__ wConv) {
    const int bid = blockIdx.x;
    const int tid = threadIdx.x;

    if (bid < 4176) {
        const int id = bid * 256 + tid;
        const int b  = id / SLOTS;
        const int i  = id % SLOTS;
        const int l  = i >> 1;
        const int p  = i & 1;
        const float* xb = x + (size_t)b * 4 * LIN + (size_t)(2 * p) * LIN;

        uint32_t w[4];
#pragma unroll
        for (int j = 0; j < 4; ++j) {
            const int ll = l + 2 * j;
            float c0 = 0.f, c1 = 0.f;
            if (ll < LIN) { c0 = xb[ll]; c1 = xb[LIN + ll]; }
            w[j] = hpack(c0, c1);
        }
        uint4 q; q.x = w[0]; q.y = w[1]; q.z = w[2]; q.w = w[3];
        g_xq[id] = q;
    } else {
        const int id = (bid - 4176) * 256 + tid;   // < 12288
        const int mh   = id / 6144;
        const int rem  = id % 6144;
        const int wm   = rem / 768;
        const int rem2 = rem % 768;
        const int lane = rem2 / 24;
        const int j    = rem2 % 24;
        const int ks   = j >> 2;
        const int rr   = j & 3;
        const int grp  = lane >> 2;
        const int tg   = lane & 3;

        const int r  = wm * 16 + grp + (rr & 1) * 8;
        const int k0 = ks * 16 + tg * 2 + (rr >> 1) * 8;        // even
        const int base = (mh * 128 + r) * KDIM + (k0 >> 2);     // k = 4g + c
        g_wA[id] = hpack(wConv[base + (k0 & 3) * GLEN],
                         wConv[base + ((k0 & 3) + 1) * GLEN]);
    }
}

// ---------------------------------------------------------------------------
// Kernel 1: implicit-GEMM conv, single-term fp16, gmem-direct fragments.
// Bias via mma C operand (no accumulator-init MOVs); running max fused with
// relu (mx >= 0 invariant); scalar sum epilogue.
// Grid: 1024 CTAs = (batch, h-half, l-half). 512 threads = 16 warps,
// warp grid 8(M) x 2(N), warp tile 16(h) x 64(l). Per-warp tile stagger.
// ---------------------------------------------------------------------------
__global__ void __launch_bounds__(512, 1)
conv_mma_kernel(const float* __restrict__ wRect) {
    __shared__ float red[512];

    const int tid   = threadIdx.x;
    const int lane  = tid & 31;
    const int wid   = tid >> 5;
    const int b     = blockIdx.x >> 2;
    const int mh    = (blockIdx.x >> 1) & 1;
    const int lq    = blockIdx.x & 1;
    const int hbase = mh * 128;
    const int L0    = lq * 1024;
    const int wm    = wid & 7;
    const int wn    = wid >> 3;
    const int grp   = lane >> 2;
    const int tg    = lane & 3;
    const int kq    = tg * 2;

    // ---- A fragments: 6 x LDG.128 from the pre-packed layout ----
    uint32_t aH[6][4];
    {
        const uint32_t* wa = g_wA + ((size_t)((mh * 8 + wm) * 32 + lane)) * 24;
#pragma unroll
        for (int ks = 0; ks < 6; ++ks)
            *(uint4*)&aH[ks][0] = *(const uint4*)(wa + ks * 4);
    }

    float rbc[4];                               // bias quad for the C operand
    rbc[0] = wRect[hbase + wm * 16 + grp];
    rbc[1] = rbc[0];
    rbc[2] = wRect[hbase + wm * 16 + 8 + grp];
    rbc[3] = rbc[2];

    const uint4* XiQ = g_xq + (size_t)b * SLOTS + 2 * L0;
    const int sbase = 2 * (wn * 64 + grp + (tg >> 1)) + (tg & 1);
    const int toff  = (wid >> 2) << 1;

    float mx[2] = {0.f, 0.f};                   // >= 0 invariant
    float sm[2] = {0.f, 0.f};

    for (int t = 0; t < NTLOC; ++t) {
        const int ta = (t + toff) & 7;
        const int base_t = sbase + 2 * ta * 128;

        float d[8][4];

        uint4 Q[10];
#pragma unroll
        for (int j = 0; j < 10; ++j)
            Q[j] = XiQ[base_t + 16 * j];

        // even ks = 0: first write per accumulator -> C = bias quad
#pragma unroll
        for (int nt = 0; nt < 8; ++nt)
            mma_f16_c(d[nt], aH[0], Q[nt].x, Q[nt].y, rbc);
        // remaining even ks
#pragma unroll
        for (int kk = 1; kk < 3; ++kk)
#pragma unroll
            for (int nt = 0; nt < 8; ++nt)
                mma_f16(d[nt], aH[2 * kk], Q[nt + kk].x, Q[nt + kk].y);
        // odd ks
#pragma unroll
        for (int kk = 0; kk < 3; ++kk)
#pragma unroll
            for (int nt = 0; nt < 8; ++nt)
                mma_f16(d[nt], aH[2 * kk + 1], Q[nt + kk].z, Q[nt + kk].w);

        if (!(lq == 1 && ta == 7)) {
#pragma unroll
            for (int nt = 0; nt < 8; ++nt)
#pragma unroll
                for (int e = 0; e < 4; ++e) {
                    const int rh = e >> 1;
                    mx[rh] = fmaxf(mx[rh], d[nt][e]);        // relu folded in
                    sm[rh] += fmaxf(d[nt][e], 0.f);
                }
        } else {
            const int lb = L0 + ta * 128 + wn * 64;
#pragma unroll
            for (int nt = 0; nt < 8; ++nt)
#pragma unroll
                for (int e = 0; e < 4; ++e) {
                    const int rh = e >> 1;
                    const int n  = lb + nt * 8 + kq + (e & 1);
                    const float r = fmaxf(d[nt][e], 0.f);
                    if (n < LOUT) {
                        mx[rh] = fmaxf(mx[rh], r);
                        sm[rh] += r;
                    }
                }
        }
    }

    // ---- lane-group reduce, cross-wn combine, write partials ----
#pragma unroll
    for (int rh = 0; rh < 2; ++rh) {
        float mv = mx[rh], sv = sm[rh];
        mv = fmaxf(mv, __shfl_xor_sync(0xffffffffu, mv, 1));
        sv +=        __shfl_xor_sync(0xffffffffu, sv, 1);
        mv = fmaxf(mv, __shfl_xor_sync(0xffffffffu, mv, 2));
        sv +=        __shfl_xor_sync(0xffffffffu, sv, 2);
        if (tg == 0) {
            const int m = wm * 16 + rh * 8 + grp;
            red[wn * 128 + m]       = mv;
            red[256 + wn * 128 + m] = sv;
        }
    }
    __syncthreads();

    if (tid < 128) {
        const float mv = fmaxf(red[tid], red[128 + tid]);
        const float sv = red[256 + tid] + red[384 + tid];
        float* pp = g_pp + (size_t)(b * 2 + lq) * TWOH;
        pp[hbase + tid]         = mv;
        pp[HNODE + hbase + tid] = sv;      // unscaled sum
    }
}

// ---------------------------------------------------------------------------
// Kernel 2: fused MLP head. 32 CTAs x 512 threads, 8 batches each.
// ---------------------------------------------------------------------------
__global__ void __launch_bounds__(512)
mlp_kernel(const float* __restrict__ wH, const float* __restrict__ wHB,
           const float* __restrict__ wNeu, const float* __restrict__ wNB,
           float* __restrict__ out) {
    __shared__ float4 prow[2][TWOH];
    __shared__ float  redsm[128];

    const int tid = threadIdx.x;
    const int b0  = blockIdx.x * 8;
    const int o   = tid;

    {
        const int i = tid;
        const float inv = 1.0f / LOUT;
#pragma unroll
        for (int h = 0; h < 2; ++h) {
            float4 v;
#pragma unroll
            for (int j = 0; j < 4; ++j) {
                const int bb = b0 + h * 4 + j;
                const float* p0 = g_pp + (size_t)(bb * 2 + 0) * TWOH;
                const float* p1 = g_pp + (size_t)(bb * 2 + 1) * TWOH;
                ((float*)&v)[j] = (i < HNODE) ? fmaxf(p0[i], p1[i])
                                              : (p0[i] + p1[i]) * inv;
            }
            prow[h][i] = v;
        }
    }
    __syncthreads();

    float a[8];
#pragma unroll
    for (int j = 0; j < 8; ++j) a[j] = 0.f;
#pragma unroll 4
    for (int i = 0; i < TWOH; ++i) {
        const float w = wH[i * TWOH + o];
        const float4 p0 = prow[0][i];
        const float4 p1 = prow[1][i];
        a[0] = fmaf(p0.x, w, a[0]);
        a[1] = fmaf(p0.y, w, a[1]);
        a[2] = fmaf(p0.z, w, a[2]);
        a[3] = fmaf(p0.w, w, a[3]);
        a[4] = fmaf(p1.x, w, a[4]);
        a[5] = fmaf(p1.y, w, a[5]);
        a[6] = fmaf(p1.z, w, a[6]);
        a[7] = fmaf(p1.w, w, a[7]);
    }

    const float hb = wHB[o];
    const float wv = wNeu[o];
    const int lane = tid & 31, wid = tid >> 5;
#pragma unroll
    for (int j = 0; j < 8; ++j) {
        float v = fmaxf(a[j] + hb, 0.f) * wv;
        v += __shfl_xor_sync(0xffffffffu, v, 16);
        v += __shfl_xor_sync(0xffffffffu, v, 8);
        v += __shfl_xor_sync(0xffffffffu, v, 4);
        v += __shfl_xor_sync(0xffffffffu, v, 2);
        v += __shfl_xor_sync(0xffffffffu, v, 1);
        if (lane == 0) redsm[j * 16 + wid] = v;
    }
    __syncthreads();

    if (tid < 8) {
        float s = 0.f;
#pragma unroll
        for (int i = 0; i < 16; ++i) s += redsm[tid * 16 + i];
        out[b0 + tid] = 0.5f * s + wNB[0];
    }
}

// ---------------------------------------------------------------------------
// Launch
// ---------------------------------------------------------------------------
extern "C" void kernel_launch(void* const* d_in, const int* in_sizes, int n_in,
                              void* d_out, int out_size) {
    const float* x     = (const float*)d_in[0];
    const float* wConv = (const float*)d_in[1];
    const float* wRect = (const float*)d_in[2];
    const float* wH    = (const float*)d_in[3];
    const float* wHB   = (const float*)d_in[4];
    const float* wNeu  = (const float*)d_in[5];
    const float* wNB   = (const float*)d_in[6];
    float* out = (float*)d_out;

    prep_kernel<<<4224, 256>>>(x, wConv);
    conv_mma_kernel<<<BATCH * 4, 512>>>(wRect);
    mlp_kernel<<<32, 512>>>(wH, wHB, wNeu, wNB, out);
}